// round 1
// baseline (speedup 1.0000x reference)
#include <cuda_runtime.h>

// ---------------------------------------------------------------------------
// TinyFormerEncoder: B=65536 independent encoders, S=16, D=32, FFN=64, fp32.
// One thread = one (batch,row). One warp = 2 batches (16 lanes each), so all
// attention data exchange is intra-warp (__syncwarp only). Packed f32x2 FMAs
// via inline PTX double fp32 throughput (128 MAC/cyc/SM). Weights transposed
// into smem once per block; k/v staged in swizzled per-warp smem buffers.
// ---------------------------------------------------------------------------

namespace {
constexpr int D   = 32;
constexpr int S   = 16;
constexpr int FFN = 64;
constexpr int BATCHES_PER_BLOCK = 8;   // 4 warps * 2 batches
constexpr int THREADS = 128;

// shared memory layout (float offsets)
constexpr int WQT = 0;        // WqT[32][32]  (j-major: row j holds Wq[:,j])
constexpr int WKT = 1024;
constexpr int WVT = 2048;
constexpr int WOT = 3072;
constexpr int W1T = 4096;     // W1T[64][32]
constexpr int W2S = 6144;     // W2 as-is [64][32] (d contiguous)
constexpr int BQo = 8192;
constexpr int BKo = 8224;
constexpr int BVo = 8256;
constexpr int BOo = 8288;
constexpr int B1o = 8320;     // 64
constexpr int B2o = 8384;     // 32
constexpr int KBo = 8416;     // k buffers: 4 warps * 2 batches * 16 * 32
constexpr int VBo = KBo + 4096;
constexpr int SMEM_FLOATS = VBo + 4096;   // 16608 floats = 66432 bytes
}

union F2U { float2 f; unsigned long long u; };

// packed fp32x2 FMA: acc += a * b (elementwise pair) — Blackwell-only PTX.
__device__ __forceinline__ void ffma2(F2U &acc, F2U a, F2U b) {
    asm("fma.rn.f32x2 %0, %1, %2, %0;" : "+l"(acc.u) : "l"(a.u), "l"(b.u));
}

// 32-length dot product: a = 16 packed f32x2 register pairs, row4 = 8 float4
// in smem (broadcast loads). sw = XOR swizzle on the float4 index (0 for
// unswizzled weight rows; t&7 for k/v buffer rows). Two accumulator chains.
__device__ __forceinline__ float dot32(const F2U *a, const float4 *row4, int sw) {
    F2U a0, a1;
    a0.f = make_float2(0.f, 0.f);
    a1.f = make_float2(0.f, 0.f);
#pragma unroll
    for (int c = 0; c < 8; c++) {
        float4 w = row4[c ^ sw];
        F2U p, q;
        p.f = make_float2(w.x, w.y);
        q.f = make_float2(w.z, w.w);
        ffma2(a0, a[2*c],   p);
        ffma2(a1, a[2*c+1], q);
    }
    return (a0.f.x + a0.f.y) + (a1.f.x + a1.f.y);
}

__device__ __forceinline__ float getx(const F2U *a, int j) {
    return (j & 1) ? a[j >> 1].f.y : a[j >> 1].f.x;
}

__global__ void __launch_bounds__(THREADS, 3)
tinyformer_kernel(const float *__restrict__ x,
                  const float *__restrict__ Wq, const float *__restrict__ bq,
                  const float *__restrict__ Wk, const float *__restrict__ bk,
                  const float *__restrict__ Wv, const float *__restrict__ bv,
                  const float *__restrict__ Wo, const float *__restrict__ bo,
                  const float *__restrict__ W1, const float *__restrict__ b1,
                  const float *__restrict__ W2, const float *__restrict__ b2,
                  float *__restrict__ out)
{
    extern __shared__ float sm[];
    const int tid = threadIdx.x;

    // ---- stage weights into smem (transposed for contiguous dot loads) ----
    for (int i = tid; i < 1024; i += THREADS) {
        int d = i >> 5, j = i & 31;
        sm[WQT + j*32 + d] = Wq[i];
        sm[WKT + j*32 + d] = Wk[i];
        sm[WVT + j*32 + d] = Wv[i];
        sm[WOT + j*32 + d] = Wo[i];
    }
    for (int i = tid; i < 2048; i += THREADS) {
        int d = i >> 6, j = i & 63;          // W1[d][j] -> W1T[j][d]
        sm[W1T + j*32 + d] = W1[i];
        sm[W2S + i] = W2[i];                 // W2[j][d] stays d-contiguous
    }
    if (tid < 32) {
        sm[BQo+tid] = bq[tid]; sm[BKo+tid] = bk[tid]; sm[BVo+tid] = bv[tid];
        sm[BOo+tid] = bo[tid]; sm[B2o+tid] = b2[tid];
    }
    if (tid < 64) sm[B1o+tid] = b1[tid];
    __syncthreads();

    const int warp  = tid >> 5;
    const int lane  = tid & 31;
    const int bslot = lane >> 4;     // which of the warp's 2 batches
    const int s     = lane & 15;     // row within sequence
    const int batch = blockIdx.x * BATCHES_PER_BLOCK + warp*2 + bslot;
    const int sw    = s & 7;

    // ---- load x row into packed register pairs ----
    const float4 *xp = reinterpret_cast<const float4*>(x + ((size_t)batch*S + s)*D);
    F2U xv[16];
#pragma unroll
    for (int c = 0; c < 8; c++) {
        float4 t = xp[c];
        xv[2*c].f   = make_float2(t.x, t.y);
        xv[2*c+1].f = make_float2(t.z, t.w);
    }

    float4 *kb4 = reinterpret_cast<float4*>(sm) + (KBo >> 2) + (warp*2 + bslot) * 128;
    float4 *vb4 = reinterpret_cast<float4*>(sm) + (VBo >> 2) + (warp*2 + bslot) * 128;

    // ---- K rows -> swizzled smem ----
#pragma unroll 2
    for (int jc = 0; jc < 8; jc++) {
        float4 r;
        r.x = dot32(xv, reinterpret_cast<const float4*>(sm + WKT + (4*jc+0)*32), 0) + sm[BKo + 4*jc+0];
        r.y = dot32(xv, reinterpret_cast<const float4*>(sm + WKT + (4*jc+1)*32), 0) + sm[BKo + 4*jc+1];
        r.z = dot32(xv, reinterpret_cast<const float4*>(sm + WKT + (4*jc+2)*32), 0) + sm[BKo + 4*jc+2];
        r.w = dot32(xv, reinterpret_cast<const float4*>(sm + WKT + (4*jc+3)*32), 0) + sm[BKo + 4*jc+3];
        kb4[s*8 + (jc ^ sw)] = r;
    }
    // ---- V rows -> swizzled smem ----
#pragma unroll 2
    for (int jc = 0; jc < 8; jc++) {
        float4 r;
        r.x = dot32(xv, reinterpret_cast<const float4*>(sm + WVT + (4*jc+0)*32), 0) + sm[BVo + 4*jc+0];
        r.y = dot32(xv, reinterpret_cast<const float4*>(sm + WVT + (4*jc+1)*32), 0) + sm[BVo + 4*jc+1];
        r.z = dot32(xv, reinterpret_cast<const float4*>(sm + WVT + (4*jc+2)*32), 0) + sm[BVo + 4*jc+2];
        r.w = dot32(xv, reinterpret_cast<const float4*>(sm + WVT + (4*jc+3)*32), 0) + sm[BVo + 4*jc+3];
        vb4[s*8 + (jc ^ sw)] = r;
    }
    // ---- Q rows -> registers (packed pairs) ----
    F2U qv[16];
#pragma unroll
    for (int jc = 0; jc < 8; jc++) {
        float q0 = dot32(xv, reinterpret_cast<const float4*>(sm + WQT + (4*jc+0)*32), 0) + sm[BQo + 4*jc+0];
        float q1 = dot32(xv, reinterpret_cast<const float4*>(sm + WQT + (4*jc+1)*32), 0) + sm[BQo + 4*jc+1];
        float q2 = dot32(xv, reinterpret_cast<const float4*>(sm + WQT + (4*jc+2)*32), 0) + sm[BQo + 4*jc+2];
        float q3 = dot32(xv, reinterpret_cast<const float4*>(sm + WQT + (4*jc+3)*32), 0) + sm[BQo + 4*jc+3];
        qv[2*jc].f   = make_float2(q0, q1);
        qv[2*jc+1].f = make_float2(q2, q3);
    }
    __syncwarp();   // k/v visible to the other lanes of this warp

    // ---- scores + thread-local softmax (each thread owns a full row) ----
    float st[16];
#pragma unroll
    for (int t = 0; t < 16; t++)
        st[t] = dot32(qv, kb4 + t*8, t & 7) * 0.17677669529663687f;  // 1/sqrt(32)

    float m = st[0];
#pragma unroll
    for (int t = 1; t < 16; t++) m = fmaxf(m, st[t]);
    float ssum = 0.f;
#pragma unroll
    for (int t = 0; t < 16; t++) { st[t] = __expf(st[t] - m); ssum += st[t]; }
    float inv = 1.0f / ssum;
#pragma unroll
    for (int t = 0; t < 16; t++) st[t] *= inv;

    // ---- context = attn @ V ----
    F2U ctx[16];
#pragma unroll
    for (int c = 0; c < 16; c++) ctx[c].f = make_float2(0.f, 0.f);
#pragma unroll
    for (int t = 0; t < 16; t++) {
        F2U at; at.f = make_float2(st[t], st[t]);
        const float4 *vr = vb4 + t*8;
        const int tsw = t & 7;
#pragma unroll
        for (int c = 0; c < 8; c++) {
            float4 w = vr[c ^ tsw];
            F2U p, q;
            p.f = make_float2(w.x, w.y);
            q.f = make_float2(w.z, w.w);
            ffma2(ctx[2*c],   at, p);
            ffma2(ctx[2*c+1], at, q);
        }
    }

    // ---- y = x + ctx @ Wo + bo ----
    F2U yv[16];
#pragma unroll
    for (int jc = 0; jc < 8; jc++) {
        float y0 = dot32(ctx, reinterpret_cast<const float4*>(sm + WOT + (4*jc+0)*32), 0) + sm[BOo + 4*jc+0] + getx(xv, 4*jc+0);
        float y1 = dot32(ctx, reinterpret_cast<const float4*>(sm + WOT + (4*jc+1)*32), 0) + sm[BOo + 4*jc+1] + getx(xv, 4*jc+1);
        float y2 = dot32(ctx, reinterpret_cast<const float4*>(sm + WOT + (4*jc+2)*32), 0) + sm[BOo + 4*jc+2] + getx(xv, 4*jc+2);
        float y3 = dot32(ctx, reinterpret_cast<const float4*>(sm + WOT + (4*jc+3)*32), 0) + sm[BOo + 4*jc+3] + getx(xv, 4*jc+3);
        yv[2*jc].f   = make_float2(y0, y1);
        yv[2*jc+1].f = make_float2(y2, y3);
    }

    // ---- FFN: z = y + relu(y@W1+b1) @ W2 + b2 ----
    F2U zv[16];
#pragma unroll
    for (int c = 0; c < 16; c++)
        zv[c].f = make_float2(yv[c].f.x + sm[B2o + 2*c], yv[c].f.y + sm[B2o + 2*c + 1]);

#pragma unroll 2
    for (int jc = 0; jc < 8; jc++) {     // 8 chunks of 8 hidden units
        float h[8];
#pragma unroll
        for (int u = 0; u < 8; u++) {
            int j = jc*8 + u;
            h[u] = fmaxf(dot32(yv, reinterpret_cast<const float4*>(sm + W1T + j*32), 0) + sm[B1o + j], 0.f);
        }
#pragma unroll
        for (int u = 0; u < 8; u++) {
            F2U hd; hd.f = make_float2(h[u], h[u]);
            const float4 *wr = reinterpret_cast<const float4*>(sm + W2S + (jc*8+u)*32);
#pragma unroll
            for (int c = 0; c < 8; c++) {
                float4 w = wr[c];
                F2U p, q;
                p.f = make_float2(w.x, w.y);
                q.f = make_float2(w.z, w.w);
                ffma2(zv[2*c],   hd, p);
                ffma2(zv[2*c+1], hd, q);
            }
        }
    }

    // ---- store z row ----
    float4 *op = reinterpret_cast<float4*>(out + ((size_t)batch*S + s)*D);
#pragma unroll
    for (int c = 0; c < 8; c++)
        op[c] = make_float4(zv[2*c].f.x, zv[2*c].f.y, zv[2*c+1].f.x, zv[2*c+1].f.y);
}

extern "C" void kernel_launch(void* const* d_in, const int* in_sizes, int n_in,
                              void* d_out, int out_size)
{
    const float* x  = (const float*)d_in[0];
    const float* Wq = (const float*)d_in[1];
    const float* bq = (const float*)d_in[2];
    const float* Wk = (const float*)d_in[3];
    const float* bk = (const float*)d_in[4];
    const float* Wv = (const float*)d_in[5];
    const float* bv = (const float*)d_in[6];
    const float* Wo = (const float*)d_in[7];
    const float* bo = (const float*)d_in[8];
    const float* W1 = (const float*)d_in[9];
    const float* b1 = (const float*)d_in[10];
    const float* W2 = (const float*)d_in[11];
    const float* b2 = (const float*)d_in[12];
    float* out = (float*)d_out;

    const int B = in_sizes[0] / (S * D);           // 65536
    const int blocks = B / BATCHES_PER_BLOCK;      // 8192
    const size_t smem = SMEM_FLOATS * sizeof(float);

    cudaFuncSetAttribute(tinyformer_kernel,
                         cudaFuncAttributeMaxDynamicSharedMemorySize, (int)smem);
    tinyformer_kernel<<<blocks, THREADS, smem>>>(x, Wq, bq, Wk, bk, Wv, bv,
                                                 Wo, bo, W1, b1, W2, b2, out);
}

// round 2
// speedup vs baseline: 1.3453x; 1.3453x over previous
#include <cuda_runtime.h>

// ---------------------------------------------------------------------------
// TinyFormerEncoder R2: 2 rows per thread. B=65536, S=16, D=32, FFN=64, fp32.
// Warp = 4 batches; each thread owns rows s and s+8 of one batch, so every
// weight-row LDS (broadcast) and every k/v-row LDS feeds TWO dot products.
// k/v smem swizzle includes a batch-group XOR so the 4 quarter-warp broadcast
// groups hit disjoint bank quads (1 wavefront instead of 4).
// Packed fp32x2 FMAs via inline PTX.
// ---------------------------------------------------------------------------

namespace {
constexpr int D   = 32;
constexpr int S   = 16;
constexpr int FFN = 64;
constexpr int BATCHES_PER_BLOCK = 16;  // 4 warps * 4 batches
constexpr int THREADS = 128;

// shared memory layout (float offsets)
constexpr int WQT = 0;        // WqT[32][32]  (row j holds Wq[:,j])
constexpr int WKT = 1024;
constexpr int WVT = 2048;
constexpr int WOT = 3072;
constexpr int W1T = 4096;     // W1T[64][32]
constexpr int W2S = 6144;     // W2 as-is [64][32]
constexpr int BQo = 8192;
constexpr int BKo = 8224;
constexpr int BVo = 8256;
constexpr int BOo = 8288;
constexpr int B1o = 8320;     // 64
constexpr int B2o = 8384;     // 32
constexpr int KBo = 8416;     // 16 batches * 16 rows * 32 floats = 8192
constexpr int VBo = KBo + 8192;
constexpr int SMEM_FLOATS = VBo + 8192;   // 24800 floats = 99200 bytes
}

union F2U { float2 f; unsigned long long u; };

__device__ __forceinline__ void ffma2(F2U &acc, F2U a, F2U b) {
    asm("fma.rn.f32x2 %0, %1, %2, %0;" : "+l"(acc.u) : "l"(a.u), "l"(b.u));
}

// Dual-row 32-length dot: one weight-row load feeds both rows' accumulators.
__device__ __forceinline__ void dot32x2(const F2U *a, const F2U *b,
                                        const float4 *row4,
                                        float &ra, float &rb) {
    F2U a0, a1, b0, b1;
    a0.f = make_float2(0.f, 0.f); a1.f = make_float2(0.f, 0.f);
    b0.f = make_float2(0.f, 0.f); b1.f = make_float2(0.f, 0.f);
#pragma unroll
    for (int c = 0; c < 8; c++) {
        float4 w = row4[c];
        F2U p, q;
        p.f = make_float2(w.x, w.y);
        q.f = make_float2(w.z, w.w);
        ffma2(a0, a[2*c],   p);
        ffma2(a1, a[2*c+1], q);
        ffma2(b0, b[2*c],   p);
        ffma2(b1, b[2*c+1], q);
    }
    ra = (a0.f.x + a0.f.y) + (a1.f.x + a1.f.y);
    rb = (b0.f.x + b0.f.y) + (b1.f.x + b1.f.y);
}

__device__ __forceinline__ float getx(const F2U *a, int j) {
    return (j & 1) ? a[j >> 1].f.y : a[j >> 1].f.x;
}
__device__ __forceinline__ void setx(F2U *a, int j, float v) {
    if (j & 1) a[j >> 1].f.y = v; else a[j >> 1].f.x = v;
}

__global__ void __launch_bounds__(THREADS, 2)
tinyformer_kernel(const float *__restrict__ x,
                  const float *__restrict__ Wq, const float *__restrict__ bq,
                  const float *__restrict__ Wk, const float *__restrict__ bk,
                  const float *__restrict__ Wv, const float *__restrict__ bv,
                  const float *__restrict__ Wo, const float *__restrict__ bo,
                  const float *__restrict__ W1, const float *__restrict__ b1,
                  const float *__restrict__ W2, const float *__restrict__ b2,
                  float *__restrict__ out)
{
    extern __shared__ float sm[];
    const int tid = threadIdx.x;

    // ---- stage weights (transposed) + biases into smem ----
    for (int i = tid; i < 1024; i += THREADS) {
        int d = i >> 5, j = i & 31;
        sm[WQT + j*32 + d] = Wq[i];
        sm[WKT + j*32 + d] = Wk[i];
        sm[WVT + j*32 + d] = Wv[i];
        sm[WOT + j*32 + d] = Wo[i];
    }
    for (int i = tid; i < 2048; i += THREADS) {
        int d = i >> 6, j = i & 63;
        sm[W1T + j*32 + d] = W1[i];
        sm[W2S + i] = W2[i];
    }
    if (tid < 32) {
        sm[BQo+tid] = bq[tid]; sm[BKo+tid] = bk[tid]; sm[BVo+tid] = bv[tid];
        sm[BOo+tid] = bo[tid]; sm[B2o+tid] = b2[tid];
    }
    if (tid < 64) sm[B1o+tid] = b1[tid];
    __syncthreads();

    const int warp = tid >> 5;
    const int lane = tid & 31;
    const int bw   = lane >> 3;        // batch within warp (0..3)
    const int r0   = lane & 7;         // thread owns rows r0 and r0+8
    const int bl   = warp*4 + bw;      // batch within block
    const size_t batch = (size_t)blockIdx.x * BATCHES_PER_BLOCK + bl;
    const int bsw  = bw << 1;          // batch-group bank-spread term
    const int ssw  = r0 ^ bsw;         // store swizzle (both rows: s&7 == r0)

    // ---- load the two x rows into packed register pairs ----
    const float4 *xpA = reinterpret_cast<const float4*>(x + (batch*S + r0    )*D);
    const float4 *xpB = reinterpret_cast<const float4*>(x + (batch*S + r0 + 8)*D);
    F2U xA[16], xB[16];
#pragma unroll
    for (int c = 0; c < 8; c++) {
        float4 t = xpA[c];
        xA[2*c].f   = make_float2(t.x, t.y);
        xA[2*c+1].f = make_float2(t.z, t.w);
        float4 u = xpB[c];
        xB[2*c].f   = make_float2(u.x, u.y);
        xB[2*c+1].f = make_float2(u.z, u.w);
    }

    float4 *kb4 = reinterpret_cast<float4*>(sm) + (KBo >> 2) + bl * 128;
    float4 *vb4 = reinterpret_cast<float4*>(sm) + (VBo >> 2) + bl * 128;

    // ---- K rows (both) -> swizzled smem ----
#pragma unroll 2
    for (int jc = 0; jc < 8; jc++) {
        float4 bi = reinterpret_cast<const float4*>(sm + BKo)[jc];
        float a0,a1,a2,a3,b0,b1,b2v,b3;
        dot32x2(xA, xB, reinterpret_cast<const float4*>(sm + WKT + (4*jc+0)*32), a0, b0);
        dot32x2(xA, xB, reinterpret_cast<const float4*>(sm + WKT + (4*jc+1)*32), a1, b1);
        dot32x2(xA, xB, reinterpret_cast<const float4*>(sm + WKT + (4*jc+2)*32), a2, b2v);
        dot32x2(xA, xB, reinterpret_cast<const float4*>(sm + WKT + (4*jc+3)*32), a3, b3);
        kb4[r0*8     + (jc ^ ssw)] = make_float4(a0+bi.x, a1+bi.y, a2+bi.z, a3+bi.w);
        kb4[(r0+8)*8 + (jc ^ ssw)] = make_float4(b0+bi.x, b1+bi.y, b2v+bi.z, b3+bi.w);
    }
    // ---- V rows (both) -> swizzled smem ----
#pragma unroll 2
    for (int jc = 0; jc < 8; jc++) {
        float4 bi = reinterpret_cast<const float4*>(sm + BVo)[jc];
        float a0,a1,a2,a3,b0,b1,b2v,b3;
        dot32x2(xA, xB, reinterpret_cast<const float4*>(sm + WVT + (4*jc+0)*32), a0, b0);
        dot32x2(xA, xB, reinterpret_cast<const float4*>(sm + WVT + (4*jc+1)*32), a1, b1);
        dot32x2(xA, xB, reinterpret_cast<const float4*>(sm + WVT + (4*jc+2)*32), a2, b2v);
        dot32x2(xA, xB, reinterpret_cast<const float4*>(sm + WVT + (4*jc+3)*32), a3, b3);
        vb4[r0*8     + (jc ^ ssw)] = make_float4(a0+bi.x, a1+bi.y, a2+bi.z, a3+bi.w);
        vb4[(r0+8)*8 + (jc ^ ssw)] = make_float4(b0+bi.x, b1+bi.y, b2v+bi.z, b3+bi.w);
    }
    // ---- Q rows (both) -> registers ----
    F2U qA[16], qB[16];
#pragma unroll 2
    for (int jc = 0; jc < 8; jc++) {
        float4 bi = reinterpret_cast<const float4*>(sm + BQo)[jc];
        float a0,a1,a2,a3,b0,b1,b2v,b3;
        dot32x2(xA, xB, reinterpret_cast<const float4*>(sm + WQT + (4*jc+0)*32), a0, b0);
        dot32x2(xA, xB, reinterpret_cast<const float4*>(sm + WQT + (4*jc+1)*32), a1, b1);
        dot32x2(xA, xB, reinterpret_cast<const float4*>(sm + WQT + (4*jc+2)*32), a2, b2v);
        dot32x2(xA, xB, reinterpret_cast<const float4*>(sm + WQT + (4*jc+3)*32), a3, b3);
        qA[2*jc].f   = make_float2(a0+bi.x, a1+bi.y);
        qA[2*jc+1].f = make_float2(a2+bi.z, a3+bi.w);
        qB[2*jc].f   = make_float2(b0+bi.x, b1+bi.y);
        qB[2*jc+1].f = make_float2(b2v+bi.z, b3+bi.w);
    }
    __syncwarp();

    // ---- scores for both rows: each k row loaded once ----
    const float SCALE = 0.17677669529663687f;  // 1/sqrt(32)
    float stA[16], stB[16];
#pragma unroll 2
    for (int t = 0; t < 16; t++) {
        const float4 *kr = kb4 + t*8;
        const int tsw = (t & 7) ^ bsw;
        F2U c0,c1,d0,d1;
        c0.f = make_float2(0.f,0.f); c1.f = make_float2(0.f,0.f);
        d0.f = make_float2(0.f,0.f); d1.f = make_float2(0.f,0.f);
#pragma unroll
        for (int c = 0; c < 8; c++) {
            float4 w = kr[c ^ tsw];
            F2U p, q;
            p.f = make_float2(w.x, w.y);
            q.f = make_float2(w.z, w.w);
            ffma2(c0, qA[2*c],   p);
            ffma2(c1, qA[2*c+1], q);
            ffma2(d0, qB[2*c],   p);
            ffma2(d1, qB[2*c+1], q);
        }
        stA[t] = ((c0.f.x+c0.f.y)+(c1.f.x+c1.f.y)) * SCALE;
        stB[t] = ((d0.f.x+d0.f.y)+(d1.f.x+d1.f.y)) * SCALE;
    }

    // ---- softmax (thread-local, per row) ----
    {
        float mA = stA[0], mB = stB[0];
#pragma unroll
        for (int t = 1; t < 16; t++) { mA = fmaxf(mA, stA[t]); mB = fmaxf(mB, stB[t]); }
        float sA = 0.f, sB = 0.f;
#pragma unroll
        for (int t = 0; t < 16; t++) {
            stA[t] = __expf(stA[t] - mA); sA += stA[t];
            stB[t] = __expf(stB[t] - mB); sB += stB[t];
        }
        float iA = 1.0f / sA, iB = 1.0f / sB;
#pragma unroll
        for (int t = 0; t < 16; t++) { stA[t] *= iA; stB[t] *= iB; }
    }

    // ---- context = attn @ V: each v row loaded once for both rows ----
    F2U cA[16], cB[16];
#pragma unroll
    for (int c = 0; c < 16; c++) { cA[c].f = make_float2(0.f,0.f); cB[c].f = make_float2(0.f,0.f); }
#pragma unroll 2
    for (int t = 0; t < 16; t++) {
        const float4 *vr = vb4 + t*8;
        const int tsw = (t & 7) ^ bsw;
        F2U aA, aB;
        aA.f = make_float2(stA[t], stA[t]);
        aB.f = make_float2(stB[t], stB[t]);
#pragma unroll
        for (int c = 0; c < 8; c++) {
            float4 w = vr[c ^ tsw];
            F2U p, q;
            p.f = make_float2(w.x, w.y);
            q.f = make_float2(w.z, w.w);
            ffma2(cA[2*c],   aA, p);
            ffma2(cA[2*c+1], aA, q);
            ffma2(cB[2*c],   aB, p);
            ffma2(cB[2*c+1], aB, q);
        }
    }

    // ---- y = x + ctx @ Wo + bo  (overwrites xA/xB in place) ----
#pragma unroll 2
    for (int jc = 0; jc < 8; jc++) {
        float4 bi = reinterpret_cast<const float4*>(sm + BOo)[jc];
        float ba[4] = {bi.x, bi.y, bi.z, bi.w};
#pragma unroll
        for (int u = 0; u < 4; u++) {
            int j = 4*jc + u;
            float ya, yb;
            dot32x2(cA, cB, reinterpret_cast<const float4*>(sm + WOT + j*32), ya, yb);
            setx(xA, j, getx(xA, j) + ya + ba[u]);
            setx(xB, j, getx(xB, j) + yb + ba[u]);
        }
    }

    // ---- FFN: z = y + relu(y@W1+b1) @ W2 + b2 ----
    F2U zA[16], zB[16];
#pragma unroll
    for (int c = 0; c < 8; c++) {
        float4 bb = reinterpret_cast<const float4*>(sm + B2o)[c];
        zA[2*c].f   = make_float2(xA[2*c].f.x   + bb.x, xA[2*c].f.y   + bb.y);
        zA[2*c+1].f = make_float2(xA[2*c+1].f.x + bb.z, xA[2*c+1].f.y + bb.w);
        zB[2*c].f   = make_float2(xB[2*c].f.x   + bb.x, xB[2*c].f.y   + bb.y);
        zB[2*c+1].f = make_float2(xB[2*c+1].f.x + bb.z, xB[2*c+1].f.y + bb.w);
    }

#pragma unroll 2
    for (int jc = 0; jc < 8; jc++) {        // 8 chunks of 8 hidden units
        float4 bh0 = reinterpret_cast<const float4*>(sm + B1o)[2*jc];
        float4 bh1 = reinterpret_cast<const float4*>(sm + B1o)[2*jc+1];
        float bh[8] = {bh0.x,bh0.y,bh0.z,bh0.w, bh1.x,bh1.y,bh1.z,bh1.w};
        float hA[8], hB[8];
#pragma unroll
        for (int u = 0; u < 8; u++) {
            int j = jc*8 + u;
            float ha, hb;
            dot32x2(xA, xB, reinterpret_cast<const float4*>(sm + W1T + j*32), ha, hb);
            hA[u] = fmaxf(ha + bh[u], 0.f);
            hB[u] = fmaxf(hb + bh[u], 0.f);
        }
#pragma unroll
        for (int u = 0; u < 8; u++) {
            F2U aA, aB;
            aA.f = make_float2(hA[u], hA[u]);
            aB.f = make_float2(hB[u], hB[u]);
            const float4 *wr = reinterpret_cast<const float4*>(sm + W2S + (jc*8+u)*32);
#pragma unroll
            for (int c = 0; c < 8; c++) {
                float4 w = wr[c];
                F2U p, q;
                p.f = make_float2(w.x, w.y);
                q.f = make_float2(w.z, w.w);
                ffma2(zA[2*c],   aA, p);
                ffma2(zA[2*c+1], aA, q);
                ffma2(zB[2*c],   aB, p);
                ffma2(zB[2*c+1], aB, q);
            }
        }
    }

    // ---- store both z rows ----
    float4 *opA = reinterpret_cast<float4*>(out + (batch*S + r0    )*D);
    float4 *opB = reinterpret_cast<float4*>(out + (batch*S + r0 + 8)*D);
#pragma unroll
    for (int c = 0; c < 8; c++) {
        opA[c] = make_float4(zA[2*c].f.x, zA[2*c].f.y, zA[2*c+1].f.x, zA[2*c+1].f.y);
        opB[c] = make_float4(zB[2*c].f.x, zB[2*c].f.y, zB[2*c+1].f.x, zB[2*c+1].f.y);
    }
}

extern "C" void kernel_launch(void* const* d_in, const int* in_sizes, int n_in,
                              void* d_out, int out_size)
{
    const float* x  = (const float*)d_in[0];
    const float* Wq = (const float*)d_in[1];
    const float* bq = (const float*)d_in[2];
    const float* Wk = (const float*)d_in[3];
    const float* bk = (const float*)d_in[4];
    const float* Wv = (const float*)d_in[5];
    const float* bv = (const float*)d_in[6];
    const float* Wo = (const float*)d_in[7];
    const float* bo = (const float*)d_in[8];
    const float* W1 = (const float*)d_in[9];
    const float* b1 = (const float*)d_in[10];
    const float* W2 = (const float*)d_in[11];
    const float* b2 = (const float*)d_in[12];
    float* out = (float*)d_out;

    const int B = in_sizes[0] / (S * D);                 // 65536
    const int blocks = B / BATCHES_PER_BLOCK;            // 4096
    const size_t smem = SMEM_FLOATS * sizeof(float);     // 99200 B

    cudaFuncSetAttribute(tinyformer_kernel,
                         cudaFuncAttributeMaxDynamicSharedMemorySize, (int)smem);
    tinyformer_kernel<<<blocks, THREADS, smem>>>(x, Wq, bq, Wk, bk, Wv, bv,
                                                 Wo, bo, W1, b1, W2, b2, out);
}